// round 9
// baseline (speedup 1.0000x reference)
#include <cuda_runtime.h>
#include <cstdint>

// Embedding gather: out[row, :] = weight[ids[row], :]
// ids: [8192] int32, weight: [32000, 1024] f32, out: [8192, 1024] f32.
//
// R4: L2::evict_last weight reads encoded as 256-bit ld.global.nc.v8.b32
// (ptxas requires v8.b32/v4.b64 with the evict_last modifier on sm_103).
// 256 threads = 2 row-lanes x 128 threads; each thread gathers 32B from
// 4 different rows (4 independent LDG.256 in flight). 8 rows per CTA.

#define DIM        1024
#define ROWS       8
#define THREADS    256
#define LANES      2                 // row-lanes per CTA
#define ROWS_PER_LANE (ROWS / LANES) // 4

struct v8 { uint32_t r[8]; };

__device__ __forceinline__ v8 ldg_evict_last_256(const void* p)
{
    v8 v;
    asm volatile(
        "ld.global.nc.L2::evict_last.v8.b32 {%0,%1,%2,%3,%4,%5,%6,%7}, [%8];"
        : "=r"(v.r[0]), "=r"(v.r[1]), "=r"(v.r[2]), "=r"(v.r[3]),
          "=r"(v.r[4]), "=r"(v.r[5]), "=r"(v.r[6]), "=r"(v.r[7])
        : "l"(p));
    return v;
}

__device__ __forceinline__ void stg_256(void* p, const v8& v)
{
    // two STG.128
    float4* f = reinterpret_cast<float4*>(p);
    f[0] = make_float4(__uint_as_float(v.r[0]), __uint_as_float(v.r[1]),
                       __uint_as_float(v.r[2]), __uint_as_float(v.r[3]));
    f[1] = make_float4(__uint_as_float(v.r[4]), __uint_as_float(v.r[5]),
                       __uint_as_float(v.r[6]), __uint_as_float(v.r[7]));
}

__global__ void __launch_bounds__(THREADS, 8)
embed_gather_kernel(const int* __restrict__ ids,
                    const float* __restrict__ weight,
                    float* __restrict__ out)
{
    const int base = blockIdx.x * ROWS;
    const int t    = threadIdx.x;
    const int lane = t >> 7;          // 0 or 1
    const int col  = (t & 127) * 8;   // float offset within row (32B chunks)

    // 4 ids for this lane: rows base + 2*r + lane, r = 0..3
    int id[ROWS_PER_LANE];
#pragma unroll
    for (int r = 0; r < ROWS_PER_LANE; r++)
        id[r] = __ldg(ids + base + 2 * r + lane);

    // 4 independent 256-bit gathers with L2 retention hint.
    v8 v[ROWS_PER_LANE];
#pragma unroll
    for (int r = 0; r < ROWS_PER_LANE; r++)
        v[r] = ldg_evict_last_256(weight + (size_t)id[r] * DIM + col);

#pragma unroll
    for (int r = 0; r < ROWS_PER_LANE; r++) {
        size_t orow = (size_t)(base + 2 * r + lane) * DIM + col;
        stg_256(out + orow, v[r]);
    }
}

extern "C" void kernel_launch(void* const* d_in, const int* in_sizes, int n_in,
                              void* d_out, int out_size)
{
    const int*   ids    = (const int*)d_in[0];
    const float* weight = (const float*)d_in[1];
    float*       out    = (float*)d_out;

    const int n_rows = in_sizes[0];         // 8192
    const int grid   = n_rows / ROWS;       // 1024

    embed_gather_kernel<<<grid, THREADS>>>(ids, weight, out);
}

// round 10
// speedup vs baseline: 1.3761x; 1.3761x over previous
#include <cuda_runtime.h>
#include <cstdint>

// Embedding gather via TMA bulk copies: out[row,:] = weight[ids[row],:]
// ids: [8192] i32, weight: [32000,1024] f32, out: [8192,1024] f32.
//
// R5: bypass the L1tex/LSU path entirely. Each CTA (1 warp) handles 8 rows:
//   - 8 pipelined cp.async.bulk G->S loads (4KB each, per-stage mbarrier)
//   - per stage: wait mbarrier, cp.async.bulk S->G store
// grid = 1024 CTAs, single wave. All bulk traffic rides the async proxy.

#define DIM       1024
#define ROW_BYTES (DIM * 4)   // 4096
#define ROWS      8
#define THREADS   32

__device__ __forceinline__ void mbar_init(uint32_t a, uint32_t cnt) {
    asm volatile("mbarrier.init.shared.b64 [%0], %1;" :: "r"(a), "r"(cnt) : "memory");
}
__device__ __forceinline__ void mbar_expect_tx(uint32_t a, uint32_t bytes) {
    asm volatile("mbarrier.arrive.expect_tx.shared.b64 _, [%0], %1;"
                 :: "r"(a), "r"(bytes) : "memory");
}
__device__ __forceinline__ void mbar_wait(uint32_t a, uint32_t parity) {
    uint32_t done;
    asm volatile(
        "{\n\t.reg .pred p;\n\t"
        "mbarrier.try_wait.parity.acquire.cta.shared::cta.b64 p, [%1], %2;\n\t"
        "selp.b32 %0, 1, 0, p;\n\t}"
        : "=r"(done) : "r"(a), "r"(parity) : "memory");
    if (!done) {
        asm volatile(
            "{\n\t.reg .pred P1;\n\t"
            "W_%=:\n\t"
            "mbarrier.try_wait.parity.acquire.cta.shared::cta.b64 P1, [%0], %1, 0x989680;\n\t"
            "@P1 bra.uni D_%=;\n\t"
            "bra.uni W_%=;\n\t"
            "D_%=:\n\t}"
            :: "r"(a), "r"(parity) : "memory");
    }
}
__device__ __forceinline__ void bulk_g2s(uint32_t dst_s, const void* src_g,
                                         uint32_t bytes, uint32_t mbar) {
    asm volatile(
        "cp.async.bulk.shared::cta.global.mbarrier::complete_tx::bytes "
        "[%0], [%1], %2, [%3];"
        :: "r"(dst_s), "l"(src_g), "r"(bytes), "r"(mbar) : "memory");
}
__device__ __forceinline__ void bulk_s2g(void* dst_g, uint32_t src_s, uint32_t bytes) {
    asm volatile(
        "cp.async.bulk.global.shared::cta.bulk_group [%0], [%1], %2;"
        :: "l"(dst_g), "r"(src_s), "r"(bytes) : "memory");
}

__global__ void __launch_bounds__(THREADS)
embed_tma_kernel(const int* __restrict__ ids,
                 const float* __restrict__ weight,
                 float* __restrict__ out)
{
    __shared__ alignas(128) char     buf[ROWS][ROW_BYTES];
    __shared__ alignas(8)   uint64_t mbar[ROWS];

    const int base = blockIdx.x * ROWS;

    if (threadIdx.x == 0) {
        uint32_t mb[ROWS], bf[ROWS];
#pragma unroll
        for (int s = 0; s < ROWS; s++) {
            mb[s] = (uint32_t)__cvta_generic_to_shared(&mbar[s]);
            bf[s] = (uint32_t)__cvta_generic_to_shared(&buf[s][0]);
            mbar_init(mb[s], 1);
        }
        // make mbarrier inits visible to the async proxy before TMA uses them
        asm volatile("fence.proxy.async.shared::cta;" ::: "memory");

        // Issue all 8 gather loads back-to-back (32KB in flight).
#pragma unroll
        for (int s = 0; s < ROWS; s++) {
            const int id = __ldg(ids + base + s);
            mbar_expect_tx(mb[s], ROW_BYTES);
            bulk_g2s(bf[s], (const char*)weight + (size_t)id * ROW_BYTES,
                     ROW_BYTES, mb[s]);
        }

        // Drain in order: as each load lands, stream it out.
#pragma unroll
        for (int s = 0; s < ROWS; s++) {
            mbar_wait(mb[s], 0);
            bulk_s2g(out + (size_t)(base + s) * DIM, bf[s], ROW_BYTES);
        }
        asm volatile("cp.async.bulk.commit_group;" ::: "memory");
        // smem is read by the bulk stores; must complete before CTA exit.
        asm volatile("cp.async.bulk.wait_group.read 0;" ::: "memory");
    }
}

extern "C" void kernel_launch(void* const* d_in, const int* in_sizes, int n_in,
                              void* d_out, int out_size)
{
    const int*   ids    = (const int*)d_in[0];
    const float* weight = (const float*)d_in[1];
    float*       out    = (float*)d_out;

    const int n_rows = in_sizes[0];        // 8192
    const int grid   = n_rows / ROWS;      // 1024

    embed_tma_kernel<<<grid, THREADS>>>(ids, weight, out);
}